// round 2
// baseline (speedup 1.0000x reference)
#include <cuda_runtime.h>
#include <math.h>

// Problem constants
namespace {
constexpr int Bz  = 4;
constexpr int SQL = 2048;
constexpr int SKL = 2048;
constexpr int Dm  = 1024;
constexpr int Hn  = 16;
constexpr int DH  = 64;      // Dm / Hn
constexpr int Mrows = Bz * SQL;  // 8192
constexpr float LN_EPS = 1e-6f;
}

// Scratch (static device globals: allocation-free)
__device__ float g_qp[Mrows * Dm];
__device__ float g_kp[Bz * SKL * Dm];
__device__ float g_vp[Bz * SKL * Dm];
__device__ float g_at[Mrows * Dm];
__device__ float g_x [Mrows * Dm];
__device__ float g_y [Mrows * Dm];

// ---------------------------------------------------------------------------
// SGEMM: C[M,N] = A[M,K] @ W[K,N] + bias[N]   (row-major, all dims % 128 == 0,
// K % 8 == 0). 128x128 block tile, 8x8 per thread, BK=8, 256 threads.
// ---------------------------------------------------------------------------
__global__ __launch_bounds__(256, 2) void sgemm_bias(
    const float* __restrict__ A, const float* __restrict__ W,
    const float* __restrict__ bias, float* __restrict__ C,
    int M, int N, int K)
{
    __shared__ float As[8][128];
    __shared__ float Bs[8][128];

    const int t  = threadIdx.x;
    const int n0 = blockIdx.x * 128;
    const int m0 = blockIdx.y * 128;
    const int tx = t & 15;
    const int ty = t >> 4;

    const int la_m = t >> 1;          // 0..127
    const int la_k = (t & 1) * 4;     // 0 or 4
    const int lb_k = t >> 5;          // 0..7
    const int lb_n = (t & 31) * 4;    // 0..124

    float acc[8][8];
#pragma unroll
    for (int i = 0; i < 8; i++)
#pragma unroll
        for (int j = 0; j < 8; j++) acc[i][j] = 0.f;

    const float* Aptr = A + (size_t)(m0 + la_m) * K + la_k;
    const float* Wptr = W + (size_t)lb_k * N + n0 + lb_n;

    for (int k0 = 0; k0 < K; k0 += 8) {
        float4 a = *(const float4*)(Aptr + k0);
        float4 b = *(const float4*)(Wptr + (size_t)k0 * N);
        As[la_k + 0][la_m] = a.x;
        As[la_k + 1][la_m] = a.y;
        As[la_k + 2][la_m] = a.z;
        As[la_k + 3][la_m] = a.w;
        *(float4*)&Bs[lb_k][lb_n] = b;
        __syncthreads();

#pragma unroll
        for (int kk = 0; kk < 8; kk++) {
            float4 a0 = *(float4*)&As[kk][ty * 8];
            float4 a1 = *(float4*)&As[kk][ty * 8 + 4];
            float4 b0 = *(float4*)&Bs[kk][tx * 8];
            float4 b1 = *(float4*)&Bs[kk][tx * 8 + 4];
            float af[8] = {a0.x, a0.y, a0.z, a0.w, a1.x, a1.y, a1.z, a1.w};
            float bf[8] = {b0.x, b0.y, b0.z, b0.w, b1.x, b1.y, b1.z, b1.w};
#pragma unroll
            for (int i = 0; i < 8; i++)
#pragma unroll
                for (int j = 0; j < 8; j++)
                    acc[i][j] += af[i] * bf[j];
        }
        __syncthreads();
    }

#pragma unroll
    for (int i = 0; i < 8; i++) {
        const size_t row = (size_t)(m0 + ty * 8 + i);
#pragma unroll
        for (int j = 0; j < 8; j += 4) {
            int col = n0 + tx * 8 + j;
            float4 o;
            o.x = acc[i][j + 0] + bias[col + 0];
            o.y = acc[i][j + 1] + bias[col + 1];
            o.z = acc[i][j + 2] + bias[col + 2];
            o.w = acc[i][j + 3] + bias[col + 3];
            *(float4*)&C[row * N + col] = o;
        }
    }
}

// ---------------------------------------------------------------------------
// Flash attention, fp32. One block = 64 q-rows of one (b,h). Tiles of 64 keys.
// Mask is int32 (jax bool -> harness int32).
// ---------------------------------------------------------------------------
struct AttnSmem {
    float Qs[64][68];
    float Ks[64][68];
    float Vs[64][68];
    float Ps[64][68];
    float m_s[64];
    float l_s[64];
    float alpha_s[64];
    int msk[64];
};

__global__ __launch_bounds__(256) void attn_kernel(
    const float* __restrict__ qp, const float* __restrict__ kp,
    const float* __restrict__ vp, const int* __restrict__ mask,
    float* __restrict__ out)
{
    extern __shared__ char smem_raw[];
    AttnSmem& sm = *reinterpret_cast<AttnSmem*>(smem_raw);

    const int t  = threadIdx.x;
    const int q0 = blockIdx.x * 64;
    const int b  = blockIdx.y >> 4;     // / Hn
    const int h  = blockIdx.y & 15;     // % Hn
    const float scale = 0.03125f;       // 1/sqrt(1024)

    // Load + pre-scale Q tile
    const float* qbase = qp + (size_t)(b * SQL + q0) * Dm + h * DH;
#pragma unroll
    for (int i = 0; i < 4; i++) {
        int u = t + 256 * i;            // 0..1023  (64 rows * 16 float4)
        int r = u >> 4, c4 = (u & 15) * 4;
        float4 qv = *(const float4*)(qbase + (size_t)r * Dm + c4);
        qv.x *= scale; qv.y *= scale; qv.z *= scale; qv.w *= scale;
        *(float4*)&sm.Qs[r][c4] = qv;
    }
    if (t < 64) { sm.m_s[t] = -INFINITY; sm.l_s[t] = 0.f; }

    const int tx = t & 15;
    const int ty = t >> 4;
    float o[4][4];
#pragma unroll
    for (int i = 0; i < 4; i++)
#pragma unroll
        for (int j = 0; j < 4; j++) o[i][j] = 0.f;

    const float* kbase = kp + (size_t)b * SKL * Dm + h * DH;
    const float* vbase = vp + (size_t)b * SKL * Dm + h * DH;
    const int* mbase = mask + (size_t)b * SKL;

    for (int k0 = 0; k0 < SKL; k0 += 64) {
        __syncthreads();   // protect shared tiles from previous iteration
#pragma unroll
        for (int i = 0; i < 4; i++) {
            int u = t + 256 * i;
            int r = u >> 4, c4 = (u & 15) * 4;
            *(float4*)&sm.Ks[r][c4] = *(const float4*)(kbase + (size_t)(k0 + r) * Dm + c4);
            *(float4*)&sm.Vs[r][c4] = *(const float4*)(vbase + (size_t)(k0 + r) * Dm + c4);
        }
        if (t < 64) sm.msk[t] = mbase[k0 + t];
        __syncthreads();

        // S = (Q*scale) @ K^T,  4x4 per thread
        float s[4][4];
#pragma unroll
        for (int i = 0; i < 4; i++)
#pragma unroll
            for (int j = 0; j < 4; j++) s[i][j] = 0.f;

#pragma unroll
        for (int d = 0; d < DH; d += 4) {
            float4 qv[4], kv[4];
#pragma unroll
            for (int i = 0; i < 4; i++) qv[i] = *(float4*)&sm.Qs[ty * 4 + i][d];
#pragma unroll
            for (int j = 0; j < 4; j++) kv[j] = *(float4*)&sm.Ks[tx * 4 + j][d];
#pragma unroll
            for (int i = 0; i < 4; i++)
#pragma unroll
                for (int j = 0; j < 4; j++)
                    s[i][j] += qv[i].x * kv[j].x + qv[i].y * kv[j].y +
                               qv[i].z * kv[j].z + qv[i].w * kv[j].w;
        }

#pragma unroll
        for (int i = 0; i < 4; i++) {
            int r = ty * 4 + i;
#pragma unroll
            for (int j = 0; j < 4; j++) {
                int c = tx * 4 + j;
                sm.Ps[r][c] = sm.msk[c] ? s[i][j] : -INFINITY;
            }
        }
        __syncthreads();

        // Online softmax: 4 threads per row (16 cols each), shuffle-reduced
        {
            int r = t >> 2, c = t & 3;
            float vals[16];
            float mloc = -INFINITY;
#pragma unroll
            for (int q = 0; q < 16; q++) {
                vals[q] = sm.Ps[r][c * 16 + q];
                mloc = fmaxf(mloc, vals[q]);
            }
            mloc = fmaxf(mloc, __shfl_xor_sync(0xffffffffu, mloc, 1));
            mloc = fmaxf(mloc, __shfl_xor_sync(0xffffffffu, mloc, 2));
            float mprev = sm.m_s[r];
            float mnew  = fmaxf(mprev, mloc);
            // mnew == -inf <=> everything masked so far: keep alpha = 1, p = 0
            float alpha = (mnew == -INFINITY) ? 1.f : __expf(mprev - mnew);
            float lsum = 0.f;
#pragma unroll
            for (int q = 0; q < 16; q++) {
                float p = (vals[q] == -INFINITY) ? 0.f : __expf(vals[q] - mnew);
                sm.Ps[r][c * 16 + q] = p;
                lsum += p;
            }
            lsum += __shfl_xor_sync(0xffffffffu, lsum, 1);
            lsum += __shfl_xor_sync(0xffffffffu, lsum, 2);
            if (c == 0) {
                sm.m_s[r] = mnew;
                sm.l_s[r] = sm.l_s[r] * alpha + lsum;
                sm.alpha_s[r] = alpha;
            }
        }
        __syncthreads();

        // O = O*alpha + P @ V
#pragma unroll
        for (int i = 0; i < 4; i++) {
            float a = sm.alpha_s[ty * 4 + i];
            o[i][0] *= a; o[i][1] *= a; o[i][2] *= a; o[i][3] *= a;
        }
        for (int kk = 0; kk < 64; kk++) {
            float4 vv = *(float4*)&sm.Vs[kk][tx * 4];
#pragma unroll
            for (int i = 0; i < 4; i++) {
                float p = sm.Ps[ty * 4 + i][kk];
                o[i][0] += p * vv.x;
                o[i][1] += p * vv.y;
                o[i][2] += p * vv.z;
                o[i][3] += p * vv.w;
            }
        }
    }

    float* obase = out + (size_t)(b * SQL + q0) * Dm + h * DH;
#pragma unroll
    for (int i = 0; i < 4; i++) {
        int r = ty * 4 + i;
        float l = sm.l_s[r];
        float linv = (l > 0.f) ? (1.f / l) : 0.f;   // fully-masked row -> 0
        float4 ov = { o[i][0] * linv, o[i][1] * linv, o[i][2] * linv, o[i][3] * linv };
        *(float4*)(obase + (size_t)r * Dm + tx * 4) = ov;
    }
}

// ---------------------------------------------------------------------------
// Fused residual (+optional ReLU on second operand) + LayerNorm over Dm=1024.
// One block per row, 256 threads, 4 elems/thread.
// ---------------------------------------------------------------------------
__global__ __launch_bounds__(256) void ln_add_kernel(
    const float* __restrict__ a, const float* __restrict__ bsrc,
    const float* __restrict__ g, const float* __restrict__ beta,
    float* __restrict__ out, int relu_b)
{
    const int row = blockIdx.x;
    const int t = threadIdx.x;
    const float* pa = a + (size_t)row * Dm;
    const float* pb = bsrc + (size_t)row * Dm;

    float4 av = *(const float4*)(pa + t * 4);
    float4 bv = *(const float4*)(pb + t * 4);
    float hv[4];
    if (relu_b) {
        hv[0] = av.x + fmaxf(bv.x, 0.f);
        hv[1] = av.y + fmaxf(bv.y, 0.f);
        hv[2] = av.z + fmaxf(bv.z, 0.f);
        hv[3] = av.w + fmaxf(bv.w, 0.f);
    } else {
        hv[0] = av.x + bv.x; hv[1] = av.y + bv.y;
        hv[2] = av.z + bv.z; hv[3] = av.w + bv.w;
    }

    float s  = hv[0] + hv[1] + hv[2] + hv[3];
    float sq = hv[0]*hv[0] + hv[1]*hv[1] + hv[2]*hv[2] + hv[3]*hv[3];
#pragma unroll
    for (int off = 16; off; off >>= 1) {
        s  += __shfl_xor_sync(0xffffffffu, s, off);
        sq += __shfl_xor_sync(0xffffffffu, sq, off);
    }
    __shared__ float ws[8], wq[8];
    int w = t >> 5, lane = t & 31;
    if (lane == 0) { ws[w] = s; wq[w] = sq; }
    __syncthreads();
    float S = 0.f, Q = 0.f;
#pragma unroll
    for (int i = 0; i < 8; i++) { S += ws[i]; Q += wq[i]; }

    const float inv_d = 1.f / (float)Dm;
    float mean = S * inv_d;
    float var  = Q * inv_d - mean * mean;
    float rs   = rsqrtf(fmaxf(var, 0.f) + LN_EPS);

    float4 gv = *(const float4*)(g + t * 4);
    float4 be = *(const float4*)(beta + t * 4);
    float4 ov;
    ov.x = (hv[0] - mean) * rs * gv.x + be.x;
    ov.y = (hv[1] - mean) * rs * gv.y + be.y;
    ov.z = (hv[2] - mean) * rs * gv.z + be.z;
    ov.w = (hv[3] - mean) * rs * gv.w + be.w;
    *(float4*)(out + (size_t)row * Dm + t * 4) = ov;
}

// ---------------------------------------------------------------------------
// Launch
// ---------------------------------------------------------------------------
extern "C" void kernel_launch(void* const* d_in, const int* in_sizes, int n_in,
                              void* d_out, int out_size)
{
    const float* q    = (const float*)d_in[0];
    const float* k    = (const float*)d_in[1];
    const float* v    = (const float*)d_in[2];
    const int*   mask = (const int*)d_in[3];     // jax bool -> harness int32
    const float* Wq   = (const float*)d_in[4];
    const float* bq   = (const float*)d_in[5];
    const float* Wk   = (const float*)d_in[6];
    const float* bk   = (const float*)d_in[7];
    const float* Wv   = (const float*)d_in[8];
    const float* bv   = (const float*)d_in[9];
    const float* Wo   = (const float*)d_in[10];
    const float* bo   = (const float*)d_in[11];
    const float* g1   = (const float*)d_in[12];
    const float* b1   = (const float*)d_in[13];
    const float* g2   = (const float*)d_in[14];
    const float* b2   = (const float*)d_in[15];

    float *qp, *kp, *vp, *at, *x, *y;
    cudaGetSymbolAddress((void**)&qp, g_qp);
    cudaGetSymbolAddress((void**)&kp, g_kp);
    cudaGetSymbolAddress((void**)&vp, g_vp);
    cudaGetSymbolAddress((void**)&at, g_at);
    cudaGetSymbolAddress((void**)&x,  g_x);
    cudaGetSymbolAddress((void**)&y,  g_y);

    cudaFuncSetAttribute(attn_kernel, cudaFuncAttributeMaxDynamicSharedMemorySize,
                         (int)sizeof(AttnSmem));

    dim3 gblk(Dm / 128, Mrows / 128);   // (8, 64)

    sgemm_bias<<<gblk, 256>>>(q, Wq, bq, qp, Mrows, Dm, Dm);
    sgemm_bias<<<gblk, 256>>>(k, Wk, bk, kp, Bz * SKL, Dm, Dm);
    sgemm_bias<<<gblk, 256>>>(v, Wv, bv, vp, Bz * SKL, Dm, Dm);

    attn_kernel<<<dim3(SQL / 64, Bz * Hn), 256, sizeof(AttnSmem)>>>(qp, kp, vp, mask, at);

    ln_add_kernel<<<Mrows, 256>>>(qp, at, g1, b1, x, 0);

    sgemm_bias<<<gblk, 256>>>(x, Wo, bo, y, Mrows, Dm, Dm);

    ln_add_kernel<<<Mrows, 256>>>(x, y, g2, b2, (float*)d_out, 1);
}

// round 3
// speedup vs baseline: 4.5037x; 4.5037x over previous
#include <cuda_runtime.h>
#include <cuda_bf16.h>
#include <math.h>

namespace {
constexpr int Bz  = 4;
constexpr int SQL = 2048;
constexpr int SKL = 2048;
constexpr int Dm  = 1024;
constexpr int Hn  = 16;
constexpr int DH  = 64;
constexpr int Mrows = Bz * SQL;      // 8192
constexpr float LN_EPS = 1e-6f;
constexpr int PK = 40;               // gemm smem pitch (bf16 elems)
constexpr int PA = 72;               // attn smem pitch (bf16 elems)
}

// Scratch
__device__ float g_qp[Mrows * Dm];
__device__ float g_kp[Bz * SKL * Dm];
__device__ float g_vp[Bz * SKL * Dm];
__device__ float g_at[Mrows * Dm];
__device__ float g_x [Mrows * Dm];
__device__ float g_y [Mrows * Dm];

// ---------------------------------------------------------------------------
// helpers
// ---------------------------------------------------------------------------
__device__ __forceinline__ unsigned pack2f(float x, float y) {
    __nv_bfloat162 h;
    h.x = __float2bfloat16_rn(x);
    h.y = __float2bfloat16_rn(y);
    return *reinterpret_cast<unsigned*>(&h);
}
__device__ __forceinline__ unsigned pack2h(__nv_bfloat16 x, __nv_bfloat16 y) {
    __nv_bfloat162 h; h.x = x; h.y = y;
    return *reinterpret_cast<unsigned*>(&h);
}

__device__ __forceinline__ void ldsm4(unsigned* r, unsigned addr) {
    asm volatile("ldmatrix.sync.aligned.m8n8.x4.shared.b16 {%0,%1,%2,%3}, [%4];"
        : "=r"(r[0]), "=r"(r[1]), "=r"(r[2]), "=r"(r[3]) : "r"(addr));
}
__device__ __forceinline__ void ldsm4t(unsigned* r, unsigned addr) {
    asm volatile("ldmatrix.sync.aligned.m8n8.x4.trans.shared.b16 {%0,%1,%2,%3}, [%4];"
        : "=r"(r[0]), "=r"(r[1]), "=r"(r[2]), "=r"(r[3]) : "r"(addr));
}
__device__ __forceinline__ void mma_bf16(float* d, const unsigned* a, const unsigned* b) {
    asm volatile(
        "mma.sync.aligned.m16n8k16.row.col.f32.bf16.bf16.f32 "
        "{%0,%1,%2,%3}, {%4,%5,%6,%7}, {%8,%9}, {%0,%1,%2,%3};"
        : "+f"(d[0]), "+f"(d[1]), "+f"(d[2]), "+f"(d[3])
        : "r"(a[0]), "r"(a[1]), "r"(a[2]), "r"(a[3]), "r"(b[0]), "r"(b[1]));
}

// ---------------------------------------------------------------------------
// GEMM: C[M,1024] = A[M,1024] @ W[1024,1024] + bias, split-bf16 (3 MMA) for
// fp32-class accuracy. Block 128x128, BK=32, 8 warps @ 64x32.
// ---------------------------------------------------------------------------
__global__ __launch_bounds__(256) void gemm_mma_split(
    const float* __restrict__ A, const float* __restrict__ W,
    const float* __restrict__ bias, float* __restrict__ C)
{
    constexpr int N = Dm, K = Dm;
    __shared__ __nv_bfloat16 As[2][128 * PK];   // [hi/lo][m*PK + k]
    __shared__ __nv_bfloat16 Bs[2][128 * PK];   // [hi/lo][n*PK + k]

    const int t = threadIdx.x;
    const int lane = t & 31, warp = t >> 5;
    const int m0 = blockIdx.y * 128, n0 = blockIdx.x * 128;
    const int wm = (warp & 1) * 64, wn = (warp >> 1) * 32;

    float acc[4][4][4] = {};

    // ldmatrix lane geometry
    const int a_r = (lane & 7) + 8 * ((lane >> 3) & 1);
    const int a_c = 8 * (lane >> 4);
    const int b_r = (lane & 7) + 8 * (lane >> 4);
    const int b_c = 8 * ((lane >> 3) & 1);

    // loader geometry
    const int lam = t >> 3;            // A row 0..31 (+32*i)
    const int lak = (t & 7) * 4;       // A col
    const int lbn = t & 127;           // B n
    const int lbk = (t >> 7) * 4;      // B k base (+8*i)

    const unsigned sA0 = (unsigned)__cvta_generic_to_shared(&As[0][0]);
    const unsigned sA1 = (unsigned)__cvta_generic_to_shared(&As[1][0]);
    const unsigned sB0 = (unsigned)__cvta_generic_to_shared(&Bs[0][0]);
    const unsigned sB1 = (unsigned)__cvta_generic_to_shared(&Bs[1][0]);

    for (int k0 = 0; k0 < K; k0 += 32) {
        // A tile 128x32 -> hi/lo
#pragma unroll
        for (int i = 0; i < 4; i++) {
            int m = lam + 32 * i;
            float4 v = *(const float4*)(A + (size_t)(m0 + m) * K + k0 + lak);
            __nv_bfloat16 h0 = __float2bfloat16_rn(v.x);
            __nv_bfloat16 h1 = __float2bfloat16_rn(v.y);
            __nv_bfloat16 h2 = __float2bfloat16_rn(v.z);
            __nv_bfloat16 h3 = __float2bfloat16_rn(v.w);
            __nv_bfloat16 l0 = __float2bfloat16_rn(v.x - __bfloat162float(h0));
            __nv_bfloat16 l1 = __float2bfloat16_rn(v.y - __bfloat162float(h1));
            __nv_bfloat16 l2 = __float2bfloat16_rn(v.z - __bfloat162float(h2));
            __nv_bfloat16 l3 = __float2bfloat16_rn(v.w - __bfloat162float(h3));
            uint2 hu = { pack2h(h0, h1), pack2h(h2, h3) };
            uint2 lu = { pack2h(l0, l1), pack2h(l2, l3) };
            *(uint2*)&As[0][m * PK + lak] = hu;
            *(uint2*)&As[1][m * PK + lak] = lu;
        }
        // W tile 32x128 transposed -> Bs[n][k]
#pragma unroll
        for (int i = 0; i < 4; i++) {
            int k = lbk + 8 * i;
            float w0 = W[(size_t)(k0 + k + 0) * N + n0 + lbn];
            float w1 = W[(size_t)(k0 + k + 1) * N + n0 + lbn];
            float w2 = W[(size_t)(k0 + k + 2) * N + n0 + lbn];
            float w3 = W[(size_t)(k0 + k + 3) * N + n0 + lbn];
            __nv_bfloat16 h0 = __float2bfloat16_rn(w0);
            __nv_bfloat16 h1 = __float2bfloat16_rn(w1);
            __nv_bfloat16 h2 = __float2bfloat16_rn(w2);
            __nv_bfloat16 h3 = __float2bfloat16_rn(w3);
            __nv_bfloat16 l0 = __float2bfloat16_rn(w0 - __bfloat162float(h0));
            __nv_bfloat16 l1 = __float2bfloat16_rn(w1 - __bfloat162float(h1));
            __nv_bfloat16 l2 = __float2bfloat16_rn(w2 - __bfloat162float(h2));
            __nv_bfloat16 l3 = __float2bfloat16_rn(w3 - __bfloat162float(h3));
            uint2 hu = { pack2h(h0, h1), pack2h(h2, h3) };
            uint2 lu = { pack2h(l0, l1), pack2h(l2, l3) };
            *(uint2*)&Bs[0][lbn * PK + k] = hu;
            *(uint2*)&Bs[1][lbn * PK + k] = lu;
        }
        __syncthreads();

#pragma unroll
        for (int ks = 0; ks < 2; ks++) {
            unsigned ah[4][4], al[4][4], bh[4][2], bl[4][2];
#pragma unroll
            for (int mi = 0; mi < 4; mi++) {
                unsigned off = ((wm + 16 * mi + a_r) * PK + 16 * ks + a_c) * 2;
                ldsm4(ah[mi], sA0 + off);
                ldsm4(al[mi], sA1 + off);
            }
#pragma unroll
            for (int bi = 0; bi < 2; bi++) {
                unsigned off = ((wn + 16 * bi + b_r) * PK + 16 * ks + b_c) * 2;
                unsigned r[4];
                ldsm4(r, sB0 + off);
                bh[2*bi][0] = r[0]; bh[2*bi][1] = r[1];
                bh[2*bi+1][0] = r[2]; bh[2*bi+1][1] = r[3];
                ldsm4(r, sB1 + off);
                bl[2*bi][0] = r[0]; bl[2*bi][1] = r[1];
                bl[2*bi+1][0] = r[2]; bl[2*bi+1][1] = r[3];
            }
#pragma unroll
            for (int mi = 0; mi < 4; mi++)
#pragma unroll
                for (int ni = 0; ni < 4; ni++) {
                    mma_bf16(acc[mi][ni], ah[mi], bh[ni]);
                    mma_bf16(acc[mi][ni], ah[mi], bl[ni]);
                    mma_bf16(acc[mi][ni], al[mi], bh[ni]);
                }
        }
        __syncthreads();
    }

    const int g = lane >> 2, c2 = (lane & 3) * 2;
#pragma unroll
    for (int mi = 0; mi < 4; mi++) {
        int row = m0 + wm + 16 * mi + g;
#pragma unroll
        for (int ni = 0; ni < 4; ni++) {
            int col = n0 + wn + 8 * ni + c2;
            float bx = bias[col], by = bias[col + 1];
            float2 v0 = { acc[mi][ni][0] + bx, acc[mi][ni][1] + by };
            float2 v1 = { acc[mi][ni][2] + bx, acc[mi][ni][3] + by };
            *(float2*)&C[(size_t)row * N + col] = v0;
            *(float2*)&C[(size_t)(row + 8) * N + col] = v1;
        }
    }
}

// ---------------------------------------------------------------------------
// Flash attention with bf16 mma. Block = 128 q rows x one (b,h); 8 warps,
// warp w owns q rows 16w..16w+15. K-tiles of 64 keys.
// ---------------------------------------------------------------------------
__global__ __launch_bounds__(256) void attn_mma(
    const float* __restrict__ qp, const float* __restrict__ kp,
    const float* __restrict__ vp, const int* __restrict__ mask,
    float* __restrict__ out)
{
    __shared__ __nv_bfloat16 Qs[128 * PA];
    __shared__ __nv_bfloat16 Ks[64 * PA];
    __shared__ __nv_bfloat16 Vs[64 * PA];
    __shared__ float madd[64];

    const int t = threadIdx.x, lane = t & 31, warp = t >> 5;
    const int q0 = blockIdx.x * 128;
    const int b  = blockIdx.y >> 4, h = blockIdx.y & 15;
    const float scale = 0.03125f;

    // Q tile (scaled, bf16)
    const float* qb = qp + (size_t)(b * SQL + q0) * Dm + h * DH;
#pragma unroll
    for (int i = 0; i < 8; i++) {
        int u = t + 256 * i;
        int r = u >> 4, d4 = (u & 15) * 4;
        float4 v = *(const float4*)(qb + (size_t)r * Dm + d4);
        uint2 p = { pack2f(v.x * scale, v.y * scale), pack2f(v.z * scale, v.w * scale) };
        *(uint2*)&Qs[r * PA + d4] = p;
    }
    __syncthreads();

    const unsigned sQ = (unsigned)__cvta_generic_to_shared(&Qs[0]);
    const unsigned sK = (unsigned)__cvta_generic_to_shared(&Ks[0]);
    const unsigned sV = (unsigned)__cvta_generic_to_shared(&Vs[0]);

    const int a_r = (lane & 7) + 8 * ((lane >> 3) & 1);
    const int a_c = 8 * (lane >> 4);
    const int b_r = (lane & 7) + 8 * (lane >> 4);          // non-trans (S)
    const int b_c = 8 * ((lane >> 3) & 1);
    const int t_r = (lane & 7) + 8 * ((lane >> 3) & 1);    // trans (PV)
    const int t_c = 8 * (lane >> 4);

    // loop-invariant Q a-frags
    unsigned qa[4][4];
#pragma unroll
    for (int ks = 0; ks < 4; ks++)
        ldsm4(qa[ks], sQ + ((16 * warp + a_r) * PA + 16 * ks + a_c) * 2);

    float o[8][4] = {};
    float m0s = -1e30f, m8s = -1e30f, l0 = 0.f, l8 = 0.f;

    const float* kb = kp + (size_t)b * SKL * Dm + h * DH;
    const float* vb = vp + (size_t)b * SKL * Dm + h * DH;
    const int* mb = mask + (size_t)b * SKL;

    const int g  = lane >> 2, c2 = (lane & 3) * 2;

    for (int kk0 = 0; kk0 < SKL; kk0 += 64) {
        __syncthreads();
#pragma unroll
        for (int i = 0; i < 4; i++) {
            int u = t + 256 * i;
            int r = u >> 4, d4 = (u & 15) * 4;
            float4 kv = *(const float4*)(kb + (size_t)(kk0 + r) * Dm + d4);
            *(uint2*)&Ks[r * PA + d4] = uint2{ pack2f(kv.x, kv.y), pack2f(kv.z, kv.w) };
            float4 vv = *(const float4*)(vb + (size_t)(kk0 + r) * Dm + d4);
            *(uint2*)&Vs[r * PA + d4] = uint2{ pack2f(vv.x, vv.y), pack2f(vv.z, vv.w) };
        }
        if (t < 64) madd[t] = mb[kk0 + t] ? 0.f : -1e30f;
        __syncthreads();

        // S = Q @ K^T  (fp32 accum)
        float s[8][4] = {};
#pragma unroll
        for (int ks = 0; ks < 4; ks++) {
#pragma unroll
            for (int bi = 0; bi < 4; bi++) {
                unsigned r[4];
                ldsm4(r, sK + ((16 * bi + b_r) * PA + 16 * ks + b_c) * 2);
                unsigned f0[2] = { r[0], r[1] }, f1[2] = { r[2], r[3] };
                mma_bf16(s[2 * bi],     qa[ks], f0);
                mma_bf16(s[2 * bi + 1], qa[ks], f1);
            }
        }

        // mask + online softmax (quad-local: rows g, g+8)
        float mt0 = -1e30f, mt8 = -1e30f;
#pragma unroll
        for (int j = 0; j < 8; j++) {
            float2 ma = *(float2*)&madd[8 * j + c2];
            s[j][0] += ma.x; s[j][1] += ma.y;
            s[j][2] += ma.x; s[j][3] += ma.y;
            mt0 = fmaxf(mt0, fmaxf(s[j][0], s[j][1]));
            mt8 = fmaxf(mt8, fmaxf(s[j][2], s[j][3]));
        }
        mt0 = fmaxf(mt0, __shfl_xor_sync(0xffffffffu, mt0, 1));
        mt0 = fmaxf(mt0, __shfl_xor_sync(0xffffffffu, mt0, 2));
        mt8 = fmaxf(mt8, __shfl_xor_sync(0xffffffffu, mt8, 1));
        mt8 = fmaxf(mt8, __shfl_xor_sync(0xffffffffu, mt8, 2));

        float mn0 = fmaxf(m0s, mt0), mn8 = fmaxf(m8s, mt8);
        float al0 = __expf(m0s - mn0), al8 = __expf(m8s - mn8);
        m0s = mn0; m8s = mn8;

        float lt0 = 0.f, lt8 = 0.f;
#pragma unroll
        for (int j = 0; j < 8; j++) {
            s[j][0] = __expf(s[j][0] - mn0);
            s[j][1] = __expf(s[j][1] - mn0);
            s[j][2] = __expf(s[j][2] - mn8);
            s[j][3] = __expf(s[j][3] - mn8);
            lt0 += s[j][0] + s[j][1];
            lt8 += s[j][2] + s[j][3];
        }
        lt0 += __shfl_xor_sync(0xffffffffu, lt0, 1);
        lt0 += __shfl_xor_sync(0xffffffffu, lt0, 2);
        lt8 += __shfl_xor_sync(0xffffffffu, lt8, 1);
        lt8 += __shfl_xor_sync(0xffffffffu, lt8, 2);
        l0 = l0 * al0 + lt0;
        l8 = l8 * al8 + lt8;

#pragma unroll
        for (int j = 0; j < 8; j++) {
            o[j][0] *= al0; o[j][1] *= al0;
            o[j][2] *= al8; o[j][3] *= al8;
        }

        // O += P @ V   (P from S regs, V via ldmatrix.trans)
#pragma unroll
        for (int ks = 0; ks < 4; ks++) {
            unsigned pa[4] = {
                pack2f(s[2*ks][0],   s[2*ks][1]),
                pack2f(s[2*ks][2],   s[2*ks][3]),
                pack2f(s[2*ks+1][0], s[2*ks+1][1]),
                pack2f(s[2*ks+1][2], s[2*ks+1][3])
            };
#pragma unroll
            for (int bi = 0; bi < 4; bi++) {
                unsigned r[4];
                ldsm4t(r, sV + ((16 * ks + t_r) * PA + 16 * bi + t_c) * 2);
                unsigned f0[2] = { r[0], r[1] }, f1[2] = { r[2], r[3] };
                mma_bf16(o[2 * bi],     pa, f0);
                mma_bf16(o[2 * bi + 1], pa, f1);
            }
        }
    }

    float li0 = (l0 > 0.f) ? 1.f / l0 : 0.f;
    float li8 = (l8 > 0.f) ? 1.f / l8 : 0.f;
    int row0 = b * SQL + q0 + 16 * warp + g;
    float* ob = out + (size_t)row0 * Dm + h * DH;
#pragma unroll
    for (int j = 0; j < 8; j++) {
        int col = 8 * j + c2;
        *(float2*)&ob[col] = float2{ o[j][0] * li0, o[j][1] * li0 };
        *(float2*)&ob[(size_t)8 * Dm + col] = float2{ o[j][2] * li8, o[j][3] * li8 };
    }
}

// ---------------------------------------------------------------------------
// Fused residual (+optional ReLU) + LayerNorm over Dm=1024.
// ---------------------------------------------------------------------------
__global__ __launch_bounds__(256) void ln_add_kernel(
    const float* __restrict__ a, const float* __restrict__ bsrc,
    const float* __restrict__ g, const float* __restrict__ beta,
    float* __restrict__ out, int relu_b)
{
    const int row = blockIdx.x;
    const int t = threadIdx.x;
    const float* pa = a + (size_t)row * Dm;
    const float* pb = bsrc + (size_t)row * Dm;

    float4 av = *(const float4*)(pa + t * 4);
    float4 bv = *(const float4*)(pb + t * 4);
    float hv[4];
    if (relu_b) {
        hv[0] = av.x + fmaxf(bv.x, 0.f);
        hv[1] = av.y + fmaxf(bv.y, 0.f);
        hv[2] = av.z + fmaxf(bv.z, 0.f);
        hv[3] = av.w + fmaxf(bv.w, 0.f);
    } else {
        hv[0] = av.x + bv.x; hv[1] = av.y + bv.y;
        hv[2] = av.z + bv.z; hv[3] = av.w + bv.w;
    }

    float s  = hv[0] + hv[1] + hv[2] + hv[3];
    float sq = hv[0]*hv[0] + hv[1]*hv[1] + hv[2]*hv[2] + hv[3]*hv[3];
#pragma unroll
    for (int off = 16; off; off >>= 1) {
        s  += __shfl_xor_sync(0xffffffffu, s, off);
        sq += __shfl_xor_sync(0xffffffffu, sq, off);
    }
    __shared__ float ws[8], wq[8];
    int w = t >> 5, lane = t & 31;
    if (lane == 0) { ws[w] = s; wq[w] = sq; }
    __syncthreads();
    float S = 0.f, Q = 0.f;
#pragma unroll
    for (int i = 0; i < 8; i++) { S += ws[i]; Q += wq[i]; }

    const float inv_d = 1.f / (float)Dm;
    float mean = S * inv_d;
    float var  = Q * inv_d - mean * mean;
    float rs   = rsqrtf(fmaxf(var, 0.f) + LN_EPS);

    float4 gv = *(const float4*)(g + t * 4);
    float4 be = *(const float4*)(beta + t * 4);
    float4 ov;
    ov.x = (hv[0] - mean) * rs * gv.x + be.x;
    ov.y = (hv[1] - mean) * rs * gv.y + be.y;
    ov.z = (hv[2] - mean) * rs * gv.z + be.z;
    ov.w = (hv[3] - mean) * rs * gv.w + be.w;
    *(float4*)(out + (size_t)row * Dm + t * 4) = ov;
}

// ---------------------------------------------------------------------------
// Launch
// ---------------------------------------------------------------------------
extern "C" void kernel_launch(void* const* d_in, const int* in_sizes, int n_in,
                              void* d_out, int out_size)
{
    const float* q    = (const float*)d_in[0];
    const float* k    = (const float*)d_in[1];
    const float* v    = (const float*)d_in[2];
    const int*   mask = (const int*)d_in[3];
    const float* Wq   = (const float*)d_in[4];
    const float* bq   = (const float*)d_in[5];
    const float* Wk   = (const float*)d_in[6];
    const float* bk   = (const float*)d_in[7];
    const float* Wv   = (const float*)d_in[8];
    const float* bv   = (const float*)d_in[9];
    const float* Wo   = (const float*)d_in[10];
    const float* bo   = (const float*)d_in[11];
    const float* g1   = (const float*)d_in[12];
    const float* b1   = (const float*)d_in[13];
    const float* g2   = (const float*)d_in[14];
    const float* b2   = (const float*)d_in[15];

    float *qp, *kp, *vp, *at, *x, *y;
    cudaGetSymbolAddress((void**)&qp, g_qp);
    cudaGetSymbolAddress((void**)&kp, g_kp);
    cudaGetSymbolAddress((void**)&vp, g_vp);
    cudaGetSymbolAddress((void**)&at, g_at);
    cudaGetSymbolAddress((void**)&x,  g_x);
    cudaGetSymbolAddress((void**)&y,  g_y);

    dim3 gblk(Dm / 128, Mrows / 128);   // (8, 64)

    gemm_mma_split<<<gblk, 256>>>(q, Wq, bq, qp);
    gemm_mma_split<<<gblk, 256>>>(k, Wk, bk, kp);
    gemm_mma_split<<<gblk, 256>>>(v, Wv, bv, vp);

    attn_mma<<<dim3(SQL / 128, Bz * Hn), 256>>>(qp, kp, vp, mask, at);

    ln_add_kernel<<<Mrows, 256>>>(qp, at, g1, b1, x, 0);

    gemm_mma_split<<<gblk, 256>>>(x, Wo, bo, y);

    ln_add_kernel<<<Mrows, 256>>>(x, y, g2, b2, (float*)d_out, 1);
}

// round 4
// speedup vs baseline: 4.7574x; 1.0563x over previous
#include <cuda_runtime.h>
#include <cuda_bf16.h>
#include <math.h>

namespace {
constexpr int Bz  = 4;
constexpr int SQL = 2048;
constexpr int SKL = 2048;
constexpr int Dm  = 1024;
constexpr int Hn  = 16;
constexpr int DH  = 64;
constexpr int Mrows = Bz * SQL;      // 8192
constexpr float LN_EPS = 1e-6f;
constexpr int PK = 40;               // gemm smem pitch (bf16 elems)
constexpr int PA = 72;               // attn smem pitch (bf16 elems)
constexpr int NT = SKL / 64;         // attn key tiles
}

// Scratch
__device__ float g_qp[Mrows * Dm];
__device__ float g_at[Mrows * Dm];
__device__ float g_x [Mrows * Dm];
__device__ float g_y [Mrows * Dm];
__device__ __nv_bfloat16 g_qb[Mrows * Dm];
__device__ __nv_bfloat16 g_kb[Bz * SKL * Dm];
__device__ __nv_bfloat16 g_vb[Bz * SKL * Dm];

// ---------------------------------------------------------------------------
// helpers
// ---------------------------------------------------------------------------
__device__ __forceinline__ unsigned pack2f(float x, float y) {
    __nv_bfloat162 h;
    h.x = __float2bfloat16_rn(x);
    h.y = __float2bfloat16_rn(y);
    return *reinterpret_cast<unsigned*>(&h);
}
__device__ __forceinline__ unsigned pack2h(__nv_bfloat16 x, __nv_bfloat16 y) {
    __nv_bfloat162 h; h.x = x; h.y = y;
    return *reinterpret_cast<unsigned*>(&h);
}
__device__ __forceinline__ void ldsm4(unsigned* r, unsigned addr) {
    asm volatile("ldmatrix.sync.aligned.m8n8.x4.shared.b16 {%0,%1,%2,%3}, [%4];"
        : "=r"(r[0]), "=r"(r[1]), "=r"(r[2]), "=r"(r[3]) : "r"(addr));
}
__device__ __forceinline__ void ldsm4t(unsigned* r, unsigned addr) {
    asm volatile("ldmatrix.sync.aligned.m8n8.x4.trans.shared.b16 {%0,%1,%2,%3}, [%4];"
        : "=r"(r[0]), "=r"(r[1]), "=r"(r[2]), "=r"(r[3]) : "r"(addr));
}
__device__ __forceinline__ void mma_bf16(float* d, const unsigned* a, const unsigned* b) {
    asm volatile(
        "mma.sync.aligned.m16n8k16.row.col.f32.bf16.bf16.f32 "
        "{%0,%1,%2,%3}, {%4,%5,%6,%7}, {%8,%9}, {%0,%1,%2,%3};"
        : "+f"(d[0]), "+f"(d[1]), "+f"(d[2]), "+f"(d[3])
        : "r"(a[0]), "r"(a[1]), "r"(a[2]), "r"(a[3]), "r"(b[0]), "r"(b[1]));
}
__device__ __forceinline__ void cp16(unsigned dst, const void* src) {
    asm volatile("cp.async.cg.shared.global [%0], [%1], 16;\n" :: "r"(dst), "l"(src));
}
__device__ __forceinline__ void cp4(unsigned dst, const void* src) {
    asm volatile("cp.async.ca.shared.global [%0], [%1], 4;\n" :: "r"(dst), "l"(src));
}
__device__ __forceinline__ void cp_commit() {
    asm volatile("cp.async.commit_group;\n");
}
template<int N> __device__ __forceinline__ void cp_wait() {
    asm volatile("cp.async.wait_group %0;\n" :: "n"(N));
}

// ---------------------------------------------------------------------------
// GEMM: C = A[M,1024] @ W[1024,1024] + bias, split-bf16 (3 MMA). Optional fp32
// output C and/or bf16 output Cb (scaled). Register-prefetch pipeline.
// ---------------------------------------------------------------------------
__global__ __launch_bounds__(256) void gemm_mma_split(
    const float* __restrict__ A, const float* __restrict__ W,
    const float* __restrict__ bias, float* __restrict__ C,
    __nv_bfloat16* __restrict__ Cb, float oscale)
{
    constexpr int N = Dm, K = Dm;
    __shared__ __nv_bfloat16 As[2][128 * PK];
    __shared__ __nv_bfloat16 Bs[2][128 * PK];

    const int t = threadIdx.x;
    const int lane = t & 31, warp = t >> 5;
    const int m0 = blockIdx.y * 128, n0 = blockIdx.x * 128;
    const int wm = (warp & 1) * 64, wn = (warp >> 1) * 32;

    float acc[4][4][4] = {};

    const int a_r = (lane & 7) + 8 * ((lane >> 3) & 1);
    const int a_c = 8 * (lane >> 4);
    const int b_r = (lane & 7) + 8 * (lane >> 4);
    const int b_c = 8 * ((lane >> 3) & 1);

    const int lam = t >> 3;
    const int lak = (t & 7) * 4;
    const int lbn = t & 127;
    const int lbk = (t >> 7) * 4;

    const unsigned sA0 = (unsigned)__cvta_generic_to_shared(&As[0][0]);
    const unsigned sA1 = (unsigned)__cvta_generic_to_shared(&As[1][0]);
    const unsigned sB0 = (unsigned)__cvta_generic_to_shared(&Bs[0][0]);
    const unsigned sB1 = (unsigned)__cvta_generic_to_shared(&Bs[1][0]);

    float4 ra[4];
    float  rw[4][4];

#define LOAD_TILE(k0)                                                          \
    {                                                                          \
        _Pragma("unroll")                                                      \
        for (int i = 0; i < 4; i++)                                            \
            ra[i] = *(const float4*)(A + (size_t)(m0 + lam + 32 * i) * K + (k0) + lak); \
        _Pragma("unroll")                                                      \
        for (int i = 0; i < 4; i++) {                                          \
            int kk = lbk + 8 * i;                                              \
            _Pragma("unroll")                                                  \
            for (int j = 0; j < 4; j++)                                        \
                rw[i][j] = W[(size_t)((k0) + kk + j) * N + n0 + lbn];          \
        }                                                                      \
    }

    LOAD_TILE(0);

    for (int k0 = 0; k0 < K; k0 += 32) {
        // store prefetched tile to smem (hi/lo split)
#pragma unroll
        for (int i = 0; i < 4; i++) {
            int m = lam + 32 * i;
            float4 v = ra[i];
            __nv_bfloat16 h0 = __float2bfloat16_rn(v.x);
            __nv_bfloat16 h1 = __float2bfloat16_rn(v.y);
            __nv_bfloat16 h2 = __float2bfloat16_rn(v.z);
            __nv_bfloat16 h3 = __float2bfloat16_rn(v.w);
            __nv_bfloat16 l0 = __float2bfloat16_rn(v.x - __bfloat162float(h0));
            __nv_bfloat16 l1 = __float2bfloat16_rn(v.y - __bfloat162float(h1));
            __nv_bfloat16 l2 = __float2bfloat16_rn(v.z - __bfloat162float(h2));
            __nv_bfloat16 l3 = __float2bfloat16_rn(v.w - __bfloat162float(h3));
            *(uint2*)&As[0][m * PK + lak] = uint2{ pack2h(h0, h1), pack2h(h2, h3) };
            *(uint2*)&As[1][m * PK + lak] = uint2{ pack2h(l0, l1), pack2h(l2, l3) };
        }
#pragma unroll
        for (int i = 0; i < 4; i++) {
            int kk = lbk + 8 * i;
            __nv_bfloat16 h0 = __float2bfloat16_rn(rw[i][0]);
            __nv_bfloat16 h1 = __float2bfloat16_rn(rw[i][1]);
            __nv_bfloat16 h2 = __float2bfloat16_rn(rw[i][2]);
            __nv_bfloat16 h3 = __float2bfloat16_rn(rw[i][3]);
            __nv_bfloat16 l0 = __float2bfloat16_rn(rw[i][0] - __bfloat162float(h0));
            __nv_bfloat16 l1 = __float2bfloat16_rn(rw[i][1] - __bfloat162float(h1));
            __nv_bfloat16 l2 = __float2bfloat16_rn(rw[i][2] - __bfloat162float(h2));
            __nv_bfloat16 l3 = __float2bfloat16_rn(rw[i][3] - __bfloat162float(h3));
            *(uint2*)&Bs[0][lbn * PK + kk] = uint2{ pack2h(h0, h1), pack2h(h2, h3) };
            *(uint2*)&Bs[1][lbn * PK + kk] = uint2{ pack2h(l0, l1), pack2h(l2, l3) };
        }
        __syncthreads();

        if (k0 + 32 < K) LOAD_TILE(k0 + 32);

#pragma unroll
        for (int ks = 0; ks < 2; ks++) {
            unsigned ah[4][4], al[4][4], bh[4][2], bl[4][2];
#pragma unroll
            for (int mi = 0; mi < 4; mi++) {
                unsigned off = ((wm + 16 * mi + a_r) * PK + 16 * ks + a_c) * 2;
                ldsm4(ah[mi], sA0 + off);
                ldsm4(al[mi], sA1 + off);
            }
#pragma unroll
            for (int bi = 0; bi < 2; bi++) {
                unsigned off = ((wn + 16 * bi + b_r) * PK + 16 * ks + b_c) * 2;
                unsigned r[4];
                ldsm4(r, sB0 + off);
                bh[2*bi][0] = r[0]; bh[2*bi][1] = r[1];
                bh[2*bi+1][0] = r[2]; bh[2*bi+1][1] = r[3];
                ldsm4(r, sB1 + off);
                bl[2*bi][0] = r[0]; bl[2*bi][1] = r[1];
                bl[2*bi+1][0] = r[2]; bl[2*bi+1][1] = r[3];
            }
#pragma unroll
            for (int mi = 0; mi < 4; mi++)
#pragma unroll
                for (int ni = 0; ni < 4; ni++) {
                    mma_bf16(acc[mi][ni], ah[mi], bh[ni]);
                    mma_bf16(acc[mi][ni], ah[mi], bl[ni]);
                    mma_bf16(acc[mi][ni], al[mi], bh[ni]);
                }
        }
        __syncthreads();
    }
#undef LOAD_TILE

    const int g = lane >> 2, c2 = (lane & 3) * 2;
#pragma unroll
    for (int mi = 0; mi < 4; mi++) {
        int row = m0 + wm + 16 * mi + g;
#pragma unroll
        for (int ni = 0; ni < 4; ni++) {
            int col = n0 + wn + 8 * ni + c2;
            float bx = bias[col], by = bias[col + 1];
            float v00 = acc[mi][ni][0] + bx, v01 = acc[mi][ni][1] + by;
            float v10 = acc[mi][ni][2] + bx, v11 = acc[mi][ni][3] + by;
            if (C) {
                *(float2*)&C[(size_t)row * N + col] = float2{ v00, v01 };
                *(float2*)&C[(size_t)(row + 8) * N + col] = float2{ v10, v11 };
            }
            if (Cb) {
                *(unsigned*)&Cb[(size_t)row * N + col] = pack2f(v00 * oscale, v01 * oscale);
                *(unsigned*)&Cb[(size_t)(row + 8) * N + col] = pack2f(v10 * oscale, v11 * oscale);
            }
        }
    }
}

// ---------------------------------------------------------------------------
// Flash attention, bf16 operands produced by GEMMs (Q pre-scaled by 1/32).
// Block = 128 q rows x one (b,h), 8 warps. K-tiles of 64 keys, 2-stage
// cp.async double buffering.
// ---------------------------------------------------------------------------
struct ASm {
    __nv_bfloat16 Qs[128 * PA];
    __nv_bfloat16 Ks[2][64 * PA];
    __nv_bfloat16 Vs[2][64 * PA];
    int msk[2][64];
};

__global__ __launch_bounds__(256, 2) void attn_mma(
    const __nv_bfloat16* __restrict__ qb, const __nv_bfloat16* __restrict__ kb,
    const __nv_bfloat16* __restrict__ vb, const int* __restrict__ mask,
    float* __restrict__ out)
{
    extern __shared__ char smem_raw[];
    ASm& sm = *reinterpret_cast<ASm*>(smem_raw);

    const int t = threadIdx.x, lane = t & 31, warp = t >> 5;
    const int q0 = blockIdx.x * 128;
    const int b  = blockIdx.y >> 4, h = blockIdx.y & 15;

    const __nv_bfloat16* qpb = qb + (size_t)(b * SQL + q0) * Dm + h * DH;
    const __nv_bfloat16* kpb = kb + (size_t)b * SKL * Dm + h * DH;
    const __nv_bfloat16* vpb = vb + (size_t)b * SKL * Dm + h * DH;
    const int* mb = mask + (size_t)b * SKL;

    const unsigned sQ  = (unsigned)__cvta_generic_to_shared(&sm.Qs[0]);
    const unsigned sK0 = (unsigned)__cvta_generic_to_shared(&sm.Ks[0][0]);
    const unsigned sK1 = (unsigned)__cvta_generic_to_shared(&sm.Ks[1][0]);
    const unsigned sV0 = (unsigned)__cvta_generic_to_shared(&sm.Vs[0][0]);
    const unsigned sV1 = (unsigned)__cvta_generic_to_shared(&sm.Vs[1][0]);
    const unsigned sM0 = (unsigned)__cvta_generic_to_shared(&sm.msk[0][0]);
    const unsigned sM1 = (unsigned)__cvta_generic_to_shared(&sm.msk[1][0]);

    // Q tile: 128 rows x 64 dims bf16 (plain vector loads)
#pragma unroll
    for (int i = 0; i < 4; i++) {
        int u = t + 256 * i;           // 1024 chunks of 8 bf16
        int r = u >> 3, c8 = (u & 7) * 8;
        *(uint4*)&sm.Qs[r * PA + c8] = *(const uint4*)(qpb + (size_t)r * Dm + c8);
    }

    const int kv_r  = t >> 3;          // 0..31 (+32)
    const int kv_c8 = (t & 7) * 8;

#define ISSUE_TILE(tile, sKb, sVb, sMb)                                        \
    {                                                                          \
        int kk0_ = (tile) * 64;                                                \
        _Pragma("unroll")                                                      \
        for (int i_ = 0; i_ < 2; i_++) {                                       \
            int r_ = kv_r + 32 * i_;                                           \
            cp16((sKb) + (unsigned)(r_ * PA + kv_c8) * 2,                      \
                 kpb + (size_t)(kk0_ + r_) * Dm + kv_c8);                      \
            cp16((sVb) + (unsigned)(r_ * PA + kv_c8) * 2,                      \
                 vpb + (size_t)(kk0_ + r_) * Dm + kv_c8);                      \
        }                                                                      \
        if (t < 64) cp4((sMb) + t * 4, mb + kk0_ + t);                         \
        cp_commit();                                                           \
    }

    ISSUE_TILE(0, sK0, sV0, sM0);

    const int a_r = (lane & 7) + 8 * ((lane >> 3) & 1);
    const int a_c = 8 * (lane >> 4);
    const int b_r = (lane & 7) + 8 * (lane >> 4);
    const int b_c = 8 * ((lane >> 3) & 1);
    const int t_r = (lane & 7) + 8 * ((lane >> 3) & 1);
    const int t_c = 8 * (lane >> 4);

    __syncthreads();   // Qs visible
    unsigned qa[4][4];
#pragma unroll
    for (int ks = 0; ks < 4; ks++)
        ldsm4(qa[ks], sQ + ((16 * warp + a_r) * PA + 16 * ks + a_c) * 2);

    float o[8][4] = {};
    float m0s = -1e30f, m8s = -1e30f, l0 = 0.f, l8 = 0.f;
    const int g = lane >> 2, c2 = (lane & 3) * 2;

    for (int it = 0; it < NT; it++) {
        const int buf = it & 1;
        if (it + 1 < NT) {
            if (buf == 0) ISSUE_TILE(it + 1, sK1, sV1, sM1)
            else          ISSUE_TILE(it + 1, sK0, sV0, sM0)
            cp_wait<1>();
        } else {
            cp_wait<0>();
        }
        __syncthreads();

        const unsigned sK = buf ? sK1 : sK0;
        const unsigned sV = buf ? sV1 : sV0;

        // S = Q @ K^T
        float s[8][4] = {};
#pragma unroll
        for (int ks = 0; ks < 4; ks++) {
#pragma unroll
            for (int bi = 0; bi < 4; bi++) {
                unsigned r[4];
                ldsm4(r, sK + ((16 * bi + b_r) * PA + 16 * ks + b_c) * 2);
                unsigned f0[2] = { r[0], r[1] }, f1[2] = { r[2], r[3] };
                mma_bf16(s[2 * bi],     qa[ks], f0);
                mma_bf16(s[2 * bi + 1], qa[ks], f1);
            }
        }

        // mask + online softmax
        float mt0 = -1e30f, mt8 = -1e30f;
#pragma unroll
        for (int j = 0; j < 8; j++) {
            int2 mi = *(int2*)&sm.msk[buf][8 * j + c2];
            float ax = mi.x ? 0.f : -1e30f;
            float ay = mi.y ? 0.f : -1e30f;
            s[j][0] += ax; s[j][1] += ay;
            s[j][2] += ax; s[j][3] += ay;
            mt0 = fmaxf(mt0, fmaxf(s[j][0], s[j][1]));
            mt8 = fmaxf(mt8, fmaxf(s[j][2], s[j][3]));
        }
        mt0 = fmaxf(mt0, __shfl_xor_sync(0xffffffffu, mt0, 1));
        mt0 = fmaxf(mt0, __shfl_xor_sync(0xffffffffu, mt0, 2));
        mt8 = fmaxf(mt8, __shfl_xor_sync(0xffffffffu, mt8, 1));
        mt8 = fmaxf(mt8, __shfl_xor_sync(0xffffffffu, mt8, 2));

        float mn0 = fmaxf(m0s, mt0), mn8 = fmaxf(m8s, mt8);
        float al0 = __expf(m0s - mn0), al8 = __expf(m8s - mn8);
        m0s = mn0; m8s = mn8;

        float lt0 = 0.f, lt8 = 0.f;
#pragma unroll
        for (int j = 0; j < 8; j++) {
            s[j][0] = __expf(s[j][0] - mn0);
            s[j][1] = __expf(s[j][1] - mn0);
            s[j][2] = __expf(s[j][2] - mn8);
            s[j][3] = __expf(s[j][3] - mn8);
            lt0 += s[j][0] + s[j][1];
            lt8 += s[j][2] + s[j][3];
        }
        lt0 += __shfl_xor_sync(0xffffffffu, lt0, 1);
        lt0 += __shfl_xor_sync(0xffffffffu, lt0, 2);
        lt8 += __shfl_xor_sync(0xffffffffu, lt8, 1);
        lt8 += __shfl_xor_sync(0xffffffffu, lt8, 2);
        l0 = l0 * al0 + lt0;
        l8 = l8 * al8 + lt8;

#pragma unroll
        for (int j = 0; j < 8; j++) {
            o[j][0] *= al0; o[j][1] *= al0;
            o[j][2] *= al8; o[j][3] *= al8;
        }

        // O += P @ V
#pragma unroll
        for (int ks = 0; ks < 4; ks++) {
            unsigned pa[4] = {
                pack2f(s[2*ks][0],   s[2*ks][1]),
                pack2f(s[2*ks][2],   s[2*ks][3]),
                pack2f(s[2*ks+1][0], s[2*ks+1][1]),
                pack2f(s[2*ks+1][2], s[2*ks+1][3])
            };
#pragma unroll
            for (int bi = 0; bi < 4; bi++) {
                unsigned r[4];
                ldsm4t(r, sV + ((16 * ks + t_r) * PA + 16 * bi + t_c) * 2);
                unsigned f0[2] = { r[0], r[1] }, f1[2] = { r[2], r[3] };
                mma_bf16(o[2 * bi],     pa, f0);
                mma_bf16(o[2 * bi + 1], pa, f1);
            }
        }
        __syncthreads();
    }
#undef ISSUE_TILE

    float li0 = (l0 > 0.f) ? 1.f / l0 : 0.f;
    float li8 = (l8 > 0.f) ? 1.f / l8 : 0.f;
    int row0 = b * SQL + q0 + 16 * warp + g;
    float* ob = out + (size_t)row0 * Dm + h * DH;
#pragma unroll
    for (int j = 0; j < 8; j++) {
        int col = 8 * j + c2;
        *(float2*)&ob[col] = float2{ o[j][0] * li0, o[j][1] * li0 };
        *(float2*)&ob[(size_t)8 * Dm + col] = float2{ o[j][2] * li8, o[j][3] * li8 };
    }
}

// ---------------------------------------------------------------------------
// Fused residual (+optional ReLU) + LayerNorm over Dm=1024.
// ---------------------------------------------------------------------------
__global__ __launch_bounds__(256) void ln_add_kernel(
    const float* __restrict__ a, const float* __restrict__ bsrc,
    const float* __restrict__ g, const float* __restrict__ beta,
    float* __restrict__ out, int relu_b)
{
    const int row = blockIdx.x;
    const int t = threadIdx.x;
    const float* pa = a + (size_t)row * Dm;
    const float* pb = bsrc + (size_t)row * Dm;

    float4 av = *(const float4*)(pa + t * 4);
    float4 bv = *(const float4*)(pb + t * 4);
    float hv[4];
    if (relu_b) {
        hv[0] = av.x + fmaxf(bv.x, 0.f);
        hv[1] = av.y + fmaxf(bv.y, 0.f);
        hv[2] = av.z + fmaxf(bv.z, 0.f);
        hv[3] = av.w + fmaxf(bv.w, 0.f);
    } else {
        hv[0] = av.x + bv.x; hv[1] = av.y + bv.y;
        hv[2] = av.z + bv.z; hv[3] = av.w + bv.w;
    }

    float s  = hv[0] + hv[1] + hv[2] + hv[3];
    float sq = hv[0]*hv[0] + hv[1]*hv[1] + hv[2]*hv[2] + hv[3]*hv[3];
#pragma unroll
    for (int off = 16; off; off >>= 1) {
        s  += __shfl_xor_sync(0xffffffffu, s, off);
        sq += __shfl_xor_sync(0xffffffffu, sq, off);
    }
    __shared__ float ws[8], wq[8];
    int w = t >> 5, lane = t & 31;
    if (lane == 0) { ws[w] = s; wq[w] = sq; }
    __syncthreads();
    float S = 0.f, Q = 0.f;
#pragma unroll
    for (int i = 0; i < 8; i++) { S += ws[i]; Q += wq[i]; }

    const float inv_d = 1.f / (float)Dm;
    float mean = S * inv_d;
    float var  = Q * inv_d - mean * mean;
    float rs   = rsqrtf(fmaxf(var, 0.f) + LN_EPS);

    float4 gv = *(const float4*)(g + t * 4);
    float4 be = *(const float4*)(beta + t * 4);
    float4 ov;
    ov.x = (hv[0] - mean) * rs * gv.x + be.x;
    ov.y = (hv[1] - mean) * rs * gv.y + be.y;
    ov.z = (hv[2] - mean) * rs * gv.z + be.z;
    ov.w = (hv[3] - mean) * rs * gv.w + be.w;
    *(float4*)(out + (size_t)row * Dm + t * 4) = ov;
}

// ---------------------------------------------------------------------------
// Launch
// ---------------------------------------------------------------------------
extern "C" void kernel_launch(void* const* d_in, const int* in_sizes, int n_in,
                              void* d_out, int out_size)
{
    const float* q    = (const float*)d_in[0];
    const float* k    = (const float*)d_in[1];
    const float* v    = (const float*)d_in[2];
    const int*   mask = (const int*)d_in[3];
    const float* Wq   = (const float*)d_in[4];
    const float* bq   = (const float*)d_in[5];
    const float* Wk   = (const float*)d_in[6];
    const float* bk   = (const float*)d_in[7];
    const float* Wv   = (const float*)d_in[8];
    const float* bv   = (const float*)d_in[9];
    const float* Wo   = (const float*)d_in[10];
    const float* bo   = (const float*)d_in[11];
    const float* g1   = (const float*)d_in[12];
    const float* b1   = (const float*)d_in[13];
    const float* g2   = (const float*)d_in[14];
    const float* b2   = (const float*)d_in[15];

    float *qp, *at, *x, *y;
    __nv_bfloat16 *qb, *kb, *vb;
    cudaGetSymbolAddress((void**)&qp, g_qp);
    cudaGetSymbolAddress((void**)&at, g_at);
    cudaGetSymbolAddress((void**)&x,  g_x);
    cudaGetSymbolAddress((void**)&y,  g_y);
    cudaGetSymbolAddress((void**)&qb, g_qb);
    cudaGetSymbolAddress((void**)&kb, g_kb);
    cudaGetSymbolAddress((void**)&vb, g_vb);

    cudaFuncSetAttribute(attn_mma, cudaFuncAttributeMaxDynamicSharedMemorySize,
                         (int)sizeof(ASm));

    dim3 gblk(Dm / 128, Mrows / 128);   // (8, 64)

    gemm_mma_split<<<gblk, 256>>>(q, Wq, bq, qp, qb, 0.03125f);      // Q pre-scaled
    gemm_mma_split<<<gblk, 256>>>(k, Wk, bk, nullptr, kb, 1.0f);
    gemm_mma_split<<<gblk, 256>>>(v, Wv, bv, nullptr, vb, 1.0f);

    attn_mma<<<dim3(SQL / 128, Bz * Hn), 256, sizeof(ASm)>>>(qb, kb, vb, mask, at);

    ln_add_kernel<<<Mrows, 256>>>(qp, at, g1, b1, x, 0);

    gemm_mma_split<<<gblk, 256>>>(x, Wo, bo, y, nullptr, 1.0f);

    ln_add_kernel<<<Mrows, 256>>>(x, y, g2, b2, (float*)d_out, 1);
}

// round 5
// speedup vs baseline: 4.9111x; 1.0323x over previous
#include <cuda_runtime.h>
#include <cuda_bf16.h>
#include <math.h>

namespace {
constexpr int Bz  = 4;
constexpr int SQL = 2048;
constexpr int SKL = 2048;
constexpr int Dm  = 1024;
constexpr int Hn  = 16;
constexpr int DH  = 64;
constexpr int Mrows = Bz * SQL;      // 8192
constexpr float LN_EPS = 1e-6f;
constexpr int PK = 40;               // gemm smem pitch (bf16)
constexpr int PA = 72;               // attn smem pitch (bf16)
constexpr int NT = SKL / 64;         // attn key tiles
constexpr int KT = Dm / 32;          // gemm k tiles
}

// Scratch
__device__ float g_qp[Mrows * Dm];
__device__ float g_at[Mrows * Dm];
__device__ float g_x [Mrows * Dm];
__device__ float g_y [Mrows * Dm];
__device__ __nv_bfloat16 g_qb[Mrows * Dm];
__device__ __nv_bfloat16 g_kb[Bz * SKL * Dm];
__device__ __nv_bfloat16 g_vb[Bz * SKL * Dm];
__device__ __nv_bfloat16 g_ah[Mrows * Dm];
__device__ __nv_bfloat16 g_al[Mrows * Dm];
__device__ __nv_bfloat16 g_wh[4 * Dm * Dm];   // [n][k] transposed
__device__ __nv_bfloat16 g_wl[4 * Dm * Dm];

// ---------------------------------------------------------------------------
// helpers
// ---------------------------------------------------------------------------
__device__ __forceinline__ unsigned pack2f(float x, float y) {
    __nv_bfloat162 h;
    h.x = __float2bfloat16_rn(x);
    h.y = __float2bfloat16_rn(y);
    return *reinterpret_cast<unsigned*>(&h);
}
__device__ __forceinline__ void ldsm4(unsigned* r, unsigned addr) {
    asm volatile("ldmatrix.sync.aligned.m8n8.x4.shared.b16 {%0,%1,%2,%3}, [%4];"
        : "=r"(r[0]), "=r"(r[1]), "=r"(r[2]), "=r"(r[3]) : "r"(addr));
}
__device__ __forceinline__ void ldsm4t(unsigned* r, unsigned addr) {
    asm volatile("ldmatrix.sync.aligned.m8n8.x4.trans.shared.b16 {%0,%1,%2,%3}, [%4];"
        : "=r"(r[0]), "=r"(r[1]), "=r"(r[2]), "=r"(r[3]) : "r"(addr));
}
__device__ __forceinline__ void mma_bf16(float* d, const unsigned* a, const unsigned* b) {
    asm volatile(
        "mma.sync.aligned.m16n8k16.row.col.f32.bf16.bf16.f32 "
        "{%0,%1,%2,%3}, {%4,%5,%6,%7}, {%8,%9}, {%0,%1,%2,%3};"
        : "+f"(d[0]), "+f"(d[1]), "+f"(d[2]), "+f"(d[3])
        : "r"(a[0]), "r"(a[1]), "r"(a[2]), "r"(a[3]), "r"(b[0]), "r"(b[1]));
}
__device__ __forceinline__ void cp16(unsigned dst, const void* src) {
    asm volatile("cp.async.cg.shared.global [%0], [%1], 16;\n" :: "r"(dst), "l"(src));
}
__device__ __forceinline__ void cp4(unsigned dst, const void* src) {
    asm volatile("cp.async.ca.shared.global [%0], [%1], 4;\n" :: "r"(dst), "l"(src));
}
__device__ __forceinline__ void cp_commit() {
    asm volatile("cp.async.commit_group;\n");
}
template<int N> __device__ __forceinline__ void cp_wait() {
    asm volatile("cp.async.wait_group %0;\n" :: "n"(N));
}

// ---------------------------------------------------------------------------
// split_w: W[k][n] fp32 -> Wh/Wl[n][k] bf16 (hi/lo), smem transpose.
// ---------------------------------------------------------------------------
__global__ __launch_bounds__(1024) void split_w(
    const float* __restrict__ W,
    __nv_bfloat16* __restrict__ Wh, __nv_bfloat16* __restrict__ Wl)
{
    __shared__ float tile[32][33];
    const int tx = threadIdx.x, ty = threadIdx.y;
    const int n0 = blockIdx.x * 32, k0 = blockIdx.y * 32;
    tile[ty][tx] = W[(size_t)(k0 + ty) * Dm + n0 + tx];
    __syncthreads();
    float v = tile[tx][ty];
    __nv_bfloat16 h = __float2bfloat16_rn(v);
    __nv_bfloat16 l = __float2bfloat16_rn(v - __bfloat162float(h));
    Wh[(size_t)(n0 + ty) * Dm + k0 + tx] = h;
    Wl[(size_t)(n0 + ty) * Dm + k0 + tx] = l;
}

// ---------------------------------------------------------------------------
// split_a: elementwise fp32 -> hi/lo bf16.
// ---------------------------------------------------------------------------
__global__ __launch_bounds__(256) void split_a(
    const float* __restrict__ A,
    __nv_bfloat16* __restrict__ Ah, __nv_bfloat16* __restrict__ Al)
{
    size_t i = ((size_t)blockIdx.x * 256 + threadIdx.x) * 4;
    float4 v = *(const float4*)(A + i);
    __nv_bfloat16 h0 = __float2bfloat16_rn(v.x);
    __nv_bfloat16 h1 = __float2bfloat16_rn(v.y);
    __nv_bfloat16 h2 = __float2bfloat16_rn(v.z);
    __nv_bfloat16 h3 = __float2bfloat16_rn(v.w);
    __nv_bfloat162 hu0; hu0.x = h0; hu0.y = h1;
    __nv_bfloat162 hu1; hu1.x = h2; hu1.y = h3;
    *(uint2*)(Ah + i) = uint2{ *(unsigned*)&hu0, *(unsigned*)&hu1 };
    __nv_bfloat162 lu0, lu1;
    lu0.x = __float2bfloat16_rn(v.x - __bfloat162float(h0));
    lu0.y = __float2bfloat16_rn(v.y - __bfloat162float(h1));
    lu1.x = __float2bfloat16_rn(v.z - __bfloat162float(h2));
    lu1.y = __float2bfloat16_rn(v.w - __bfloat162float(h3));
    *(uint2*)(Al + i) = uint2{ *(unsigned*)&lu0, *(unsigned*)&lu1 };
}

// ---------------------------------------------------------------------------
// GEMM on pre-split operands: C = A @ W^T_layout + bias (3-term split MMA).
// Block 128x128, BK=32, 8 warps @ 64x32. 2-stage cp.async pipeline, no
// conversions in the loop.
// ---------------------------------------------------------------------------
struct GSm {
    __nv_bfloat16 AsH[2][128 * PK];
    __nv_bfloat16 AsL[2][128 * PK];
    __nv_bfloat16 BsH[2][128 * PK];
    __nv_bfloat16 BsL[2][128 * PK];
};

__global__ __launch_bounds__(256) void gemm_bf16(
    const __nv_bfloat16* __restrict__ Ah, const __nv_bfloat16* __restrict__ Al,
    const __nv_bfloat16* __restrict__ Wh, const __nv_bfloat16* __restrict__ Wl,
    const float* __restrict__ bias, float* __restrict__ C,
    __nv_bfloat16* __restrict__ Cb, float oscale)
{
    extern __shared__ char smem_raw[];
    GSm& sm = *reinterpret_cast<GSm*>(smem_raw);

    const int t = threadIdx.x;
    const int lane = t & 31, warp = t >> 5;
    const int m0 = blockIdx.y * 128, n0 = blockIdx.x * 128;
    const int wm = (warp & 1) * 64, wn = (warp >> 1) * 32;

    float acc[4][4][4] = {};

    const int a_r = (lane & 7) + 8 * ((lane >> 3) & 1);
    const int a_c = 8 * (lane >> 4);
    const int b_r = (lane & 7) + 8 * (lane >> 4);
    const int b_c = 8 * ((lane >> 3) & 1);

    // loader: u in [0,512): r = u>>2 (0..127), c8 = (u&3)*8
    const int l_r0 = t >> 2, l_c = (t & 3) * 8;

    unsigned sAH[2], sAL[2], sBH[2], sBL[2];
#pragma unroll
    for (int s = 0; s < 2; s++) {
        sAH[s] = (unsigned)__cvta_generic_to_shared(&sm.AsH[s][0]);
        sAL[s] = (unsigned)__cvta_generic_to_shared(&sm.AsL[s][0]);
        sBH[s] = (unsigned)__cvta_generic_to_shared(&sm.BsH[s][0]);
        sBL[s] = (unsigned)__cvta_generic_to_shared(&sm.BsL[s][0]);
    }

#define ISSUE_G(kt, s)                                                         \
    {                                                                          \
        int k0_ = (kt) * 32;                                                   \
        _Pragma("unroll")                                                      \
        for (int i_ = 0; i_ < 2; i_++) {                                       \
            int r_ = l_r0 + 64 * i_;                                           \
            unsigned off_ = (unsigned)(r_ * PK + l_c) * 2;                     \
            const size_t ga_ = (size_t)(m0 + r_) * Dm + k0_ + l_c;             \
            const size_t gb_ = (size_t)(n0 + r_) * Dm + k0_ + l_c;             \
            cp16(sAH[s] + off_, Ah + ga_);                                     \
            cp16(sAL[s] + off_, Al + ga_);                                     \
            cp16(sBH[s] + off_, Wh + gb_);                                     \
            cp16(sBL[s] + off_, Wl + gb_);                                     \
        }                                                                      \
        cp_commit();                                                           \
    }

    ISSUE_G(0, 0);

    for (int kt = 0; kt < KT; kt++) {
        const int buf = kt & 1;
        __syncthreads();   // prior reads of buf^1 done before overwrite
        if (kt + 1 < KT) {
            ISSUE_G(kt + 1, buf ^ 1);
            cp_wait<1>();
        } else {
            cp_wait<0>();
        }
        __syncthreads();

#pragma unroll
        for (int ks = 0; ks < 2; ks++) {
            unsigned ah[4][4], al[4][4], bh[4][2], bl[4][2];
#pragma unroll
            for (int mi = 0; mi < 4; mi++) {
                unsigned off = ((wm + 16 * mi + a_r) * PK + 16 * ks + a_c) * 2;
                ldsm4(ah[mi], sAH[buf] + off);
                ldsm4(al[mi], sAL[buf] + off);
            }
#pragma unroll
            for (int bi = 0; bi < 2; bi++) {
                unsigned off = ((wn + 16 * bi + b_r) * PK + 16 * ks + b_c) * 2;
                unsigned r[4];
                ldsm4(r, sBH[buf] + off);
                bh[2*bi][0] = r[0]; bh[2*bi][1] = r[1];
                bh[2*bi+1][0] = r[2]; bh[2*bi+1][1] = r[3];
                ldsm4(r, sBL[buf] + off);
                bl[2*bi][0] = r[0]; bl[2*bi][1] = r[1];
                bl[2*bi+1][0] = r[2]; bl[2*bi+1][1] = r[3];
            }
#pragma unroll
            for (int mi = 0; mi < 4; mi++)
#pragma unroll
                for (int ni = 0; ni < 4; ni++) {
                    mma_bf16(acc[mi][ni], ah[mi], bh[ni]);
                    mma_bf16(acc[mi][ni], ah[mi], bl[ni]);
                    mma_bf16(acc[mi][ni], al[mi], bh[ni]);
                }
        }
    }
#undef ISSUE_G

    const int g = lane >> 2, c2 = (lane & 3) * 2;
#pragma unroll
    for (int mi = 0; mi < 4; mi++) {
        int row = m0 + wm + 16 * mi + g;
#pragma unroll
        for (int ni = 0; ni < 4; ni++) {
            int col = n0 + wn + 8 * ni + c2;
            float bx = bias[col], by = bias[col + 1];
            float v00 = acc[mi][ni][0] + bx, v01 = acc[mi][ni][1] + by;
            float v10 = acc[mi][ni][2] + bx, v11 = acc[mi][ni][3] + by;
            if (C) {
                *(float2*)&C[(size_t)row * Dm + col] = float2{ v00, v01 };
                *(float2*)&C[(size_t)(row + 8) * Dm + col] = float2{ v10, v11 };
            }
            if (Cb) {
                *(unsigned*)&Cb[(size_t)row * Dm + col] = pack2f(v00 * oscale, v01 * oscale);
                *(unsigned*)&Cb[(size_t)(row + 8) * Dm + col] = pack2f(v10 * oscale, v11 * oscale);
            }
        }
    }
}

// ---------------------------------------------------------------------------
// Flash attention (unchanged from R4): bf16 operands, Q pre-scaled, 2-stage
// cp.async, 128 q rows x (b,h), 8 warps.
// ---------------------------------------------------------------------------
struct ASm {
    __nv_bfloat16 Qs[128 * PA];
    __nv_bfloat16 Ks[2][64 * PA];
    __nv_bfloat16 Vs[2][64 * PA];
    int msk[2][64];
};

__global__ __launch_bounds__(256, 2) void attn_mma(
    const __nv_bfloat16* __restrict__ qb, const __nv_bfloat16* __restrict__ kb,
    const __nv_bfloat16* __restrict__ vb, const int* __restrict__ mask,
    float* __restrict__ out)
{
    extern __shared__ char smem_raw[];
    ASm& sm = *reinterpret_cast<ASm*>(smem_raw);

    const int t = threadIdx.x, lane = t & 31, warp = t >> 5;
    const int q0 = blockIdx.x * 128;
    const int b  = blockIdx.y >> 4, h = blockIdx.y & 15;

    const __nv_bfloat16* qpb = qb + (size_t)(b * SQL + q0) * Dm + h * DH;
    const __nv_bfloat16* kpb = kb + (size_t)b * SKL * Dm + h * DH;
    const __nv_bfloat16* vpb = vb + (size_t)b * SKL * Dm + h * DH;
    const int* mb = mask + (size_t)b * SKL;

    const unsigned sQ  = (unsigned)__cvta_generic_to_shared(&sm.Qs[0]);
    const unsigned sK0 = (unsigned)__cvta_generic_to_shared(&sm.Ks[0][0]);
    const unsigned sK1 = (unsigned)__cvta_generic_to_shared(&sm.Ks[1][0]);
    const unsigned sV0 = (unsigned)__cvta_generic_to_shared(&sm.Vs[0][0]);
    const unsigned sV1 = (unsigned)__cvta_generic_to_shared(&sm.Vs[1][0]);
    const unsigned sM0 = (unsigned)__cvta_generic_to_shared(&sm.msk[0][0]);
    const unsigned sM1 = (unsigned)__cvta_generic_to_shared(&sm.msk[1][0]);

#pragma unroll
    for (int i = 0; i < 4; i++) {
        int u = t + 256 * i;
        int r = u >> 3, c8 = (u & 7) * 8;
        *(uint4*)&sm.Qs[r * PA + c8] = *(const uint4*)(qpb + (size_t)r * Dm + c8);
    }

    const int kv_r  = t >> 3;
    const int kv_c8 = (t & 7) * 8;

#define ISSUE_TILE(tile, sKb, sVb, sMb)                                        \
    {                                                                          \
        int kk0_ = (tile) * 64;                                                \
        _Pragma("unroll")                                                      \
        for (int i_ = 0; i_ < 2; i_++) {                                       \
            int r_ = kv_r + 32 * i_;                                           \
            cp16((sKb) + (unsigned)(r_ * PA + kv_c8) * 2,                      \
                 kpb + (size_t)(kk0_ + r_) * Dm + kv_c8);                      \
            cp16((sVb) + (unsigned)(r_ * PA + kv_c8) * 2,                      \
                 vpb + (size_t)(kk0_ + r_) * Dm + kv_c8);                      \
        }                                                                      \
        if (t < 64) cp4((sMb) + t * 4, mb + kk0_ + t);                         \
        cp_commit();                                                           \
    }

    ISSUE_TILE(0, sK0, sV0, sM0);

    const int a_r = (lane & 7) + 8 * ((lane >> 3) & 1);
    const int a_c = 8 * (lane >> 4);
    const int b_r = (lane & 7) + 8 * (lane >> 4);
    const int b_c = 8 * ((lane >> 3) & 1);
    const int t_r = (lane & 7) + 8 * ((lane >> 3) & 1);
    const int t_c = 8 * (lane >> 4);

    __syncthreads();
    unsigned qa[4][4];
#pragma unroll
    for (int ks = 0; ks < 4; ks++)
        ldsm4(qa[ks], sQ + ((16 * warp + a_r) * PA + 16 * ks + a_c) * 2);

    float o[8][4] = {};
    float m0s = -1e30f, m8s = -1e30f, l0 = 0.f, l8 = 0.f;
    const int g = lane >> 2, c2 = (lane & 3) * 2;

    for (int it = 0; it < NT; it++) {
        const int buf = it & 1;
        if (it + 1 < NT) {
            if (buf == 0) ISSUE_TILE(it + 1, sK1, sV1, sM1)
            else          ISSUE_TILE(it + 1, sK0, sV0, sM0)
            cp_wait<1>();
        } else {
            cp_wait<0>();
        }
        __syncthreads();

        const unsigned sK = buf ? sK1 : sK0;
        const unsigned sV = buf ? sV1 : sV0;

        float s[8][4] = {};
#pragma unroll
        for (int ks = 0; ks < 4; ks++) {
#pragma unroll
            for (int bi = 0; bi < 4; bi++) {
                unsigned r[4];
                ldsm4(r, sK + ((16 * bi + b_r) * PA + 16 * ks + b_c) * 2);
                unsigned f0[2] = { r[0], r[1] }, f1[2] = { r[2], r[3] };
                mma_bf16(s[2 * bi],     qa[ks], f0);
                mma_bf16(s[2 * bi + 1], qa[ks], f1);
            }
        }

        float mt0 = -1e30f, mt8 = -1e30f;
#pragma unroll
        for (int j = 0; j < 8; j++) {
            int2 mi = *(int2*)&sm.msk[buf][8 * j + c2];
            float ax = mi.x ? 0.f : -1e30f;
            float ay = mi.y ? 0.f : -1e30f;
            s[j][0] += ax; s[j][1] += ay;
            s[j][2] += ax; s[j][3] += ay;
            mt0 = fmaxf(mt0, fmaxf(s[j][0], s[j][1]));
            mt8 = fmaxf(mt8, fmaxf(s[j][2], s[j][3]));
        }
        mt0 = fmaxf(mt0, __shfl_xor_sync(0xffffffffu, mt0, 1));
        mt0 = fmaxf(mt0, __shfl_xor_sync(0xffffffffu, mt0, 2));
        mt8 = fmaxf(mt8, __shfl_xor_sync(0xffffffffu, mt8, 1));
        mt8 = fmaxf(mt8, __shfl_xor_sync(0xffffffffu, mt8, 2));

        float mn0 = fmaxf(m0s, mt0), mn8 = fmaxf(m8s, mt8);
        float al0 = __expf(m0s - mn0), al8 = __expf(m8s - mn8);
        m0s = mn0; m8s = mn8;

        float lt0 = 0.f, lt8 = 0.f;
#pragma unroll
        for (int j = 0; j < 8; j++) {
            s[j][0] = __expf(s[j][0] - mn0);
            s[j][1] = __expf(s[j][1] - mn0);
            s[j][2] = __expf(s[j][2] - mn8);
            s[j][3] = __expf(s[j][3] - mn8);
            lt0 += s[j][0] + s[j][1];
            lt8 += s[j][2] + s[j][3];
        }
        lt0 += __shfl_xor_sync(0xffffffffu, lt0, 1);
        lt0 += __shfl_xor_sync(0xffffffffu, lt0, 2);
        lt8 += __shfl_xor_sync(0xffffffffu, lt8, 1);
        lt8 += __shfl_xor_sync(0xffffffffu, lt8, 2);
        l0 = l0 * al0 + lt0;
        l8 = l8 * al8 + lt8;

#pragma unroll
        for (int j = 0; j < 8; j++) {
            o[j][0] *= al0; o[j][1] *= al0;
            o[j][2] *= al8; o[j][3] *= al8;
        }

#pragma unroll
        for (int ks = 0; ks < 4; ks++) {
            unsigned pa[4] = {
                pack2f(s[2*ks][0],   s[2*ks][1]),
                pack2f(s[2*ks][2],   s[2*ks][3]),
                pack2f(s[2*ks+1][0], s[2*ks+1][1]),
                pack2f(s[2*ks+1][2], s[2*ks+1][3])
            };
#pragma unroll
            for (int bi = 0; bi < 4; bi++) {
                unsigned r[4];
                ldsm4t(r, sV + ((16 * ks + t_r) * PA + 16 * bi + t_c) * 2);
                unsigned f0[2] = { r[0], r[1] }, f1[2] = { r[2], r[3] };
                mma_bf16(o[2 * bi],     pa, f0);
                mma_bf16(o[2 * bi + 1], pa, f1);
            }
        }
        __syncthreads();
    }
#undef ISSUE_TILE

    float li0 = (l0 > 0.f) ? 1.f / l0 : 0.f;
    float li8 = (l8 > 0.f) ? 1.f / l8 : 0.f;
    int row0 = b * SQL + q0 + 16 * warp + g;
    float* ob = out + (size_t)row0 * Dm + h * DH;
#pragma unroll
    for (int j = 0; j < 8; j++) {
        int col = 8 * j + c2;
        *(float2*)&ob[col] = float2{ o[j][0] * li0, o[j][1] * li0 };
        *(float2*)&ob[(size_t)8 * Dm + col] = float2{ o[j][2] * li8, o[j][3] * li8 };
    }
}

// ---------------------------------------------------------------------------
// Fused residual (+optional ReLU) + LayerNorm over Dm=1024.
// ---------------------------------------------------------------------------
__global__ __launch_bounds__(256) void ln_add_kernel(
    const float* __restrict__ a, const float* __restrict__ bsrc,
    const float* __restrict__ g, const float* __restrict__ beta,
    float* __restrict__ out, int relu_b)
{
    const int row = blockIdx.x;
    const int t = threadIdx.x;
    const float* pa = a + (size_t)row * Dm;
    const float* pb = bsrc + (size_t)row * Dm;

    float4 av = *(const float4*)(pa + t * 4);
    float4 bv = *(const float4*)(pb + t * 4);
    float hv[4];
    if (relu_b) {
        hv[0] = av.x + fmaxf(bv.x, 0.f);
        hv[1] = av.y + fmaxf(bv.y, 0.f);
        hv[2] = av.z + fmaxf(bv.z, 0.f);
        hv[3] = av.w + fmaxf(bv.w, 0.f);
    } else {
        hv[0] = av.x + bv.x; hv[1] = av.y + bv.y;
        hv[2] = av.z + bv.z; hv[3] = av.w + bv.w;
    }

    float s  = hv[0] + hv[1] + hv[2] + hv[3];
    float sq = hv[0]*hv[0] + hv[1]*hv[1] + hv[2]*hv[2] + hv[3]*hv[3];
#pragma unroll
    for (int off = 16; off; off >>= 1) {
        s  += __shfl_xor_sync(0xffffffffu, s, off);
        sq += __shfl_xor_sync(0xffffffffu, sq, off);
    }
    __shared__ float ws[8], wq[8];
    int w = t >> 5, lane = t & 31;
    if (lane == 0) { ws[w] = s; wq[w] = sq; }
    __syncthreads();
    float S = 0.f, Q = 0.f;
#pragma unroll
    for (int i = 0; i < 8; i++) { S += ws[i]; Q += wq[i]; }

    const float inv_d = 1.f / (float)Dm;
    float mean = S * inv_d;
    float var  = Q * inv_d - mean * mean;
    float rs   = rsqrtf(fmaxf(var, 0.f) + LN_EPS);

    float4 gv = *(const float4*)(g + t * 4);
    float4 be = *(const float4*)(beta + t * 4);
    float4 ov;
    ov.x = (hv[0] - mean) * rs * gv.x + be.x;
    ov.y = (hv[1] - mean) * rs * gv.y + be.y;
    ov.z = (hv[2] - mean) * rs * gv.z + be.z;
    ov.w = (hv[3] - mean) * rs * gv.w + be.w;
    *(float4*)(out + (size_t)row * Dm + t * 4) = ov;
}

// ---------------------------------------------------------------------------
// Launch
// ---------------------------------------------------------------------------
extern "C" void kernel_launch(void* const* d_in, const int* in_sizes, int n_in,
                              void* d_out, int out_size)
{
    const float* q    = (const float*)d_in[0];
    const float* k    = (const float*)d_in[1];
    const float* v    = (const float*)d_in[2];
    const int*   mask = (const int*)d_in[3];
    const float* Wq   = (const float*)d_in[4];
    const float* bq   = (const float*)d_in[5];
    const float* Wk   = (const float*)d_in[6];
    const float* bk   = (const float*)d_in[7];
    const float* Wv   = (const float*)d_in[8];
    const float* bv   = (const float*)d_in[9];
    const float* Wo   = (const float*)d_in[10];
    const float* bo   = (const float*)d_in[11];
    const float* g1   = (const float*)d_in[12];
    const float* b1   = (const float*)d_in[13];
    const float* g2   = (const float*)d_in[14];
    const float* b2   = (const float*)d_in[15];

    float *qp, *at, *x, *y;
    __nv_bfloat16 *qb, *kb, *vb, *ah, *al, *wh, *wl;
    cudaGetSymbolAddress((void**)&qp, g_qp);
    cudaGetSymbolAddress((void**)&at, g_at);
    cudaGetSymbolAddress((void**)&x,  g_x);
    cudaGetSymbolAddress((void**)&y,  g_y);
    cudaGetSymbolAddress((void**)&qb, g_qb);
    cudaGetSymbolAddress((void**)&kb, g_kb);
    cudaGetSymbolAddress((void**)&vb, g_vb);
    cudaGetSymbolAddress((void**)&ah, g_ah);
    cudaGetSymbolAddress((void**)&al, g_al);
    cudaGetSymbolAddress((void**)&wh, g_wh);
    cudaGetSymbolAddress((void**)&wl, g_wl);

    cudaFuncSetAttribute(attn_mma, cudaFuncAttributeMaxDynamicSharedMemorySize,
                         (int)sizeof(ASm));
    cudaFuncSetAttribute(gemm_bf16, cudaFuncAttributeMaxDynamicSharedMemorySize,
                         (int)sizeof(GSm));

    const size_t WSZ = (size_t)Dm * Dm;
    dim3 wgrid(Dm / 32, Dm / 32), wblk(32, 32);
    split_w<<<wgrid, wblk>>>(Wq, wh + 0 * WSZ, wl + 0 * WSZ);
    split_w<<<wgrid, wblk>>>(Wk, wh + 1 * WSZ, wl + 1 * WSZ);
    split_w<<<wgrid, wblk>>>(Wv, wh + 2 * WSZ, wl + 2 * WSZ);
    split_w<<<wgrid, wblk>>>(Wo, wh + 3 * WSZ, wl + 3 * WSZ);

    dim3 gblk(Dm / 128, Mrows / 128);   // (8, 64)
    const int nspl = Mrows * Dm / 1024; // 8192 blocks

    split_a<<<nspl, 256>>>(q, ah, al);
    gemm_bf16<<<gblk, 256, sizeof(GSm)>>>(ah, al, wh + 0 * WSZ, wl + 0 * WSZ,
                                          bq, qp, qb, 0.03125f);
    split_a<<<nspl, 256>>>(k, ah, al);
    gemm_bf16<<<gblk, 256, sizeof(GSm)>>>(ah, al, wh + 1 * WSZ, wl + 1 * WSZ,
                                          bk, nullptr, kb, 1.0f);
    split_a<<<nspl, 256>>>(v, ah, al);
    gemm_bf16<<<gblk, 256, sizeof(GSm)>>>(ah, al, wh + 2 * WSZ, wl + 2 * WSZ,
                                          bv, nullptr, vb, 1.0f);

    attn_mma<<<dim3(SQL / 128, Bz * Hn), 256, sizeof(ASm)>>>(qb, kb, vb, mask, at);

    ln_add_kernel<<<Mrows, 256>>>(qp, at, g1, b1, x, 0);

    split_a<<<nspl, 256>>>(x, ah, al);
    gemm_bf16<<<gblk, 256, sizeof(GSm)>>>(ah, al, wh + 3 * WSZ, wl + 3 * WSZ,
                                          bo, y, nullptr, 1.0f);

    ln_add_kernel<<<Mrows, 256>>>(x, y, g2, b2, (float*)d_out, 1);
}